// round 10
// baseline (speedup 1.0000x reference)
#include <cuda_runtime.h>
#include <cstdint>

// Shapes (fixed): x:[16,16,52,52] f32, W:[16,16,9,1], B:[16,16,1], out:[16,16,16]
#define NN 16
#define CC 16
#define HH 52
#define PLANE (HH*HH)      // 2704 floats = 676 float4
#define VPP (PLANE/4)      // 676
#define KK 9
#define M_TOT 22500.0f
#define CLUSTER 8          // cluster = one n; CTA = 2 planes (512 threads)

__device__ __forceinline__ uint32_t smem_u32(const void* p) {
    uint32_t a;
    asm("{ .reg .u64 t; cvta.to.shared.u64 t, %1; cvt.u32.u64 %0, t; }" : "=r"(a) : "l"(p));
    return a;
}

// warp-wide f32 sum, broadcast to all lanes (redux.f32 unsupported on sm_103)
__device__ __forceinline__ float wsum(float v) {
#pragma unroll
    for (int off = 16; off > 0; off >>= 1)
        v += __shfl_xor_sync(0xffffffffu, v, off);
    return v;
}

__global__ void __cluster_dims__(CLUSTER, 1, 1) __launch_bounds__(512, 1)
tvar_cluster(const float* __restrict__ x, const float* __restrict__ W,
             const float* __restrict__ B, float* __restrict__ out)
{
    __shared__ float sAll[16*CC];                 // rank0 gathers contrib[o][c]
    __shared__ unsigned long long sMbar;
    __shared__ float sWarp[2][8][2];
    __shared__ float sR1[2][4], sR2[2][4];        // row sums, rows {0,1,50,51}
    __shared__ float sC1[2][2][2][2], sC2[2][2][2][2]; // [half][pair][part][col]
    __shared__ float sCor1[2][16], sCor2[2][16];  // corner values / squares

    const int tid  = threadIdx.x;
    const int w    = tid >> 5;
    const int lane = tid & 31;
    const int half = tid >> 8;                    // which plane of this CTA
    const int t    = tid & 255;
    const int s    = w & 7;                       // warp role within half
    uint32_t rank;
    asm("mov.u32 %0, %%cluster_ctarank;" : "=r"(rank));

    // init at cycle ~20; first remote arrive lands >1200 cyc later
    if (rank == 0 && tid == 0) {
        asm volatile("mbarrier.init.shared.b64 [%0], %1;"
                     :: "r"(smem_u32(&sMbar)), "r"(256u) : "memory");
    }

    const int n = blockIdx.x >> 3;
    const int c = (int)rank * 2 + half;
    const int plane = n * CC + c;
    const float*  xp = x + plane * PLANE;
    const float4* xv = (const float4*)xp;

    // ================= FRONT-BATCHED LOADS (everything in flight at once) ====
    float4 d0 = __ldg(xv + t);
    float4 d1 = __ldg(xv + t + 256);
    float4 d2 = make_float4(0.f, 0.f, 0.f, 0.f);
    const bool has2 = (t < VPP - 512);
    if (has2) d2 = __ldg(xv + t + 512);

    // strip re-loads (L2 hits on same lines; no atomics anywhere)
    float4 rowv = make_float4(0.f, 0.f, 0.f, 0.f);
    float2 colv = make_float2(0.f, 0.f);
    if (s >= 6) {                                 // rows: s=6 -> {0,1}, s=7 -> {50,51}
        if (lane < 26) rowv = __ldg(xv + (s == 6 ? 0 : 650) + lane);
    } else if (s >= 2) {                          // col pairs {0,1} / {50,51}
        const int pair = (s - 2) >> 1;
        const int r = lane + ((s - 2) & 1) * 32;
        if (r < HH) colv = __ldg((const float2*)(xp + r * HH + pair * 50));
    }

    float wreg[KK];
    float cor = 0.f;
    if (t < 16) {                                 // corners + W row (warp 0 lanes)
        const int ki = t >> 2, kj = t & 3;
        const int rr  = (ki & 2 ? 50 : 0) + (ki & 1);
        const int cc2 = (kj & 2 ? 50 : 0) + (kj & 1);
        cor = __ldg(xp + rr * HH + cc2);
        // W row is only 4B-aligned -> scalar loads (LDG.128 here traps)
        const float* wp = W + (t * CC + c) * KK;  // W[o=t, c, :]
#pragma unroll
        for (int k = 0; k < KK; k++) wreg[k] = __ldg(wp + k);
    }
    float bval = 0.f;
    if (rank == 0 && tid < 256) bval = __ldg(B + (tid >> 4) * CC + n);

    // early cluster arrive (R5-proven alignment); the WAIT is deferred to the
    // very end so it overlaps the STG drain instead of gating the output.
    asm volatile("barrier.cluster.arrive.aligned;" ::: "memory");

    // ================= TOTALS (per half-plane) ===============================
    float t1 = ((d0.x + d0.y) + (d0.z + d0.w))
             + ((d1.x + d1.y) + (d1.z + d1.w))
             + ((d2.x + d2.y) + (d2.z + d2.w));
    float t2 = d0.x*d0.x + d0.y*d0.y + d0.z*d0.z + d0.w*d0.w
             + d1.x*d1.x + d1.y*d1.y + d1.z*d1.z + d1.w*d1.w
             + d2.x*d2.x + d2.y*d2.y + d2.z*d2.z + d2.w*d2.w;
    t1 = wsum(t1);
    t2 = wsum(t2);
    if (lane == 0) { sWarp[half][s][0] = t1; sWarp[half][s][1] = t2; }

    // ================= STRIP SUMS (butterfly reductions) =====================
    if (s >= 6) {
        const float rs1 = (rowv.x + rowv.y) + (rowv.z + rowv.w);
        const float rs2 = rowv.x*rowv.x + rowv.y*rowv.y + rowv.z*rowv.z + rowv.w*rowv.w;
        const bool inA = (lane < 13);
        const bool inB = (lane >= 13) && (lane < 26);
        const float a1 = wsum(inA ? rs1 : 0.f);
        const float a2 = wsum(inA ? rs2 : 0.f);
        const float b1 = wsum(inB ? rs1 : 0.f);
        const float b2 = wsum(inB ? rs2 : 0.f);
        if (lane == 0) {
            const int rb = (s - 6) * 2;
            sR1[half][rb+0] = a1; sR2[half][rb+0] = a2;
            sR1[half][rb+1] = b1; sR2[half][rb+1] = b2;
        }
    } else if (s >= 2) {
        const int pair = (s - 2) >> 1;
        const int part = (s - 2) & 1;
        const float x1 = wsum(colv.x);
        const float x2 = wsum(colv.x * colv.x);
        const float y1 = wsum(colv.y);
        const float y2 = wsum(colv.y * colv.y);
        if (lane == 0) {
            sC1[half][pair][part][0] = x1; sC2[half][pair][part][0] = x2;
            sC1[half][pair][part][1] = y1; sC2[half][pair][part][1] = y2;
        }
    }
    if (t < 16) { sCor1[half][t] = cor; sCor2[half][t] = cor * cor; }

    __syncthreads();   // intra-CTA ordering: everything the tail needs is ready

    // ===== WINDOW SUMS + CONTRIB + DSMEM PUBLISH (warps 0 and 8; no cluster
    //       dependency — init-visibility margin >1200cyc, proven in R7) =======
    if (s == 0) {
        float s1v = 0.f, s2v = 0.f;
        if (lane < 9) {
            float tot1 = 0.f, tot2 = 0.f;
#pragma unroll
            for (int wi = 0; wi < 8; wi++) { tot1 += sWarp[half][wi][0]; tot2 += sWarp[half][wi][1]; }
            const int i = lane / 3, j = lane % 3;
            float R1[4], R2[4], C1[4], C2[4];
#pragma unroll
            for (int k = 0; k < 4; k++) {
                R1[k] = sR1[half][k]; R2[k] = sR2[half][k];
                C1[k] = sC1[half][k>>1][0][k&1] + sC1[half][k>>1][1][k&1];
                C2[k] = sC2[half][k>>1][0][k&1] + sC2[half][k>>1][1][k&1];
            }
            const float top1 = (i == 0) ? 0.f : (i == 1) ? R1[0] : R1[0] + R1[1];
            const float top2 = (i == 0) ? 0.f : (i == 1) ? R2[0] : R2[0] + R2[1];
            const float bot1 = (i == 0) ? R1[2] + R1[3] : (i == 1) ? R1[3] : 0.f;
            const float bot2 = (i == 0) ? R2[2] + R2[3] : (i == 1) ? R2[3] : 0.f;
            const float lef1 = (j == 0) ? 0.f : (j == 1) ? C1[0] : C1[0] + C1[1];
            const float lef2 = (j == 0) ? 0.f : (j == 1) ? C2[0] : C2[0] + C2[1];
            const float rig1 = (j == 0) ? C1[2] + C1[3] : (j == 1) ? C1[3] : 0.f;
            const float rig2 = (j == 0) ? C2[2] + C2[3] : (j == 1) ? C2[3] : 0.f;
            const int er0 = (i == 0) ? 2 : 0;
            const int er1 = (i == 2) ? 1 : 3;
            const int ec0 = (j == 0) ? 2 : 0;
            const int ec1 = (j == 2) ? 1 : 3;
            const float co1 = sCor1[half][er0*4+ec0] + sCor1[half][er0*4+ec1]
                            + sCor1[half][er1*4+ec0] + sCor1[half][er1*4+ec1];
            const float co2 = sCor2[half][er0*4+ec0] + sCor2[half][er0*4+ec1]
                            + sCor2[half][er1*4+ec0] + sCor2[half][er1*4+ec1];
            s1v = tot1 - top1 - bot1 - lef1 - rig1 + co1;
            s2v = tot2 - top2 - bot2 - lef2 - rig2 + co2;
        }
        float S1k[KK], S2k[KK];
#pragma unroll
        for (int k = 0; k < KK; k++) {
            S1k[k] = __shfl_sync(0xffffffffu, s1v, k);
            S2k[k] = __shfl_sync(0xffffffffu, s2v, k);
        }
        if (lane < 16) {
            float size = 0.f, A = 0.f, Bs = 0.f;
#pragma unroll
            for (int k = 0; k < KK; k++) {
                const float wv = wreg[k];
                size += wv;
                Bs = fmaf(wv,      S1k[k], Bs);
                A  = fmaf(wv * wv, S2k[k], A);
            }
            const float contrib = (A - Bs * Bs * (1.0f / M_TOT)) / size;
            // store into rank0's sAll[o][c] (transposed) and release-arrive
            uint32_t dst = smem_u32(&sAll[lane * CC + c]);
            uint32_t rem;
            asm("mapa.shared::cluster.u32 %0, %1, %2;" : "=r"(rem) : "r"(dst), "r"(0u));
            asm volatile("st.shared::cluster.f32 [%0], %1;" :: "r"(rem), "f"(contrib) : "memory");
            uint32_t mb = smem_u32(&sMbar);
            uint32_t remb;
            asm("mapa.shared::cluster.u32 %0, %1, %2;" : "=r"(remb) : "r"(mb), "r"(0u));
            asm volatile("mbarrier.arrive.release.cluster.shared::cluster.b64 _, [%0];"
                         :: "r"(remb) : "memory");
        }
    }

    // ================= RANK-0 EPILOGUE (gated by mbarrier only) ==============
    if (rank == 0 && tid < 256) {
        const uint32_t mb = smem_u32(&sMbar);
        asm volatile(
            "{\n\t.reg .pred P;\n\t"
            "W%=:\n\t"
            "mbarrier.try_wait.parity.acquire.cluster.shared::cta.b64 P, [%0], %1, 0x989680;\n\t"
            "@!P bra W%=;\n\t}"
            :: "r"(mb), "r"(0u) : "memory");
        const int a = tid >> 4;
        const int o = tid & 15;
        const float4* row = (const float4*)&sAll[o * CC];
        const float4 v0 = row[0], v1 = row[1], v2 = row[2], v3 = row[3];
        const float acc = ((v0.x + v0.y) + (v0.z + v0.w))
                        + ((v1.x + v1.y) + (v1.z + v1.w))
                        + ((v2.x + v2.y) + (v2.z + v2.w))
                        + ((v3.x + v3.y) + (v3.z + v3.w));
        out[a * 256 + n * 16 + o] = acc + bval;
    }

    // deferred cluster wait: satisfied long ago (all arrived early); overlaps
    // the output STG drain instead of sitting in front of it.
    asm volatile("barrier.cluster.wait.aligned;" ::: "memory");
}

extern "C" void kernel_launch(void* const* d_in, const int* in_sizes, int n_in,
                              void* d_out, int out_size)
{
    const float* x = (const float*)d_in[0];
    const float* W = (const float*)d_in[1];
    const float* B = (const float*)d_in[2];
    float* out = (float*)d_out;
    tvar_cluster<<<NN * CLUSTER, 512>>>(x, W, B, out);
}